// round 9
// baseline (speedup 1.0000x reference)
#include <cuda_runtime.h>
#include <cuda_bf16.h>
#include <math.h>
#include <math_constants.h>

#define HB 512
#define WB 512
#define NB (HB*WB)          // 262144 BEV cells
#define NC 64               // channels
#define NBATCH 2
#define HR 64
#define WR 2048
#define NG 8                // row groups (8 rows each)
#define CAP 320             // smem-staged cells per column; overflow -> direct path
#define CAP2 512            // bucket capacity per (col,group)
#define SMEM_FEAT (CAP * NC * 4)   // 80 KB
#define FLAG_DIRECT 0x80000000u

// device scratch
__device__ float          g_rho[NB];
__device__ unsigned char  g_rowlow[NB];
__device__ unsigned short g_colb[NB];
__device__ unsigned short g_slotp[NB];
__device__ int            g_cellof[WR * CAP];
__device__ int            g_cnt[WR];
__device__ int            g_cnt2[NBATCH * WR * NG];
__device__ unsigned int   g_item[(size_t)NBATCH * WR * NG * CAP2];
__device__ float          g_featT[(size_t)NBATCH * NB * NC];        // [B][N][C]
__device__ float          g_scratch[(size_t)NBATCH * WR * HR * NC]; // [B][col][r][c]

__device__ __forceinline__ float th_maxf()   { return (float)(3.0 * (CUDART_PI / 180.0)); }
__device__ __forceinline__ float th_rangef() {
    double tmax = 3.0 * (CUDART_PI / 180.0);
    double tmin = -25.0 * (CUDART_PI / 180.0);
    return (float)(tmax - tmin);
}
__device__ __forceinline__ float phi_minf()   { return (float)(-CUDART_PI); }
__device__ __forceinline__ float phi_rangef() { return (float)(2.0 * CUDART_PI); }

__device__ __forceinline__ int row_from_theta(float theta) {
    float v = __fmul_rn(__fdiv_rn(__fsub_rn(th_maxf(), theta), th_rangef()), 63.0f);
    v = rintf(v);
    v = fminf(fmaxf(v, 0.0f), 63.0f);
    return (int)v;
}

// ---------------- kernels ----------------
__global__ void k_zero() {
    int t = blockIdx.x * blockDim.x + threadIdx.x;
    if (t < WR) g_cnt[t] = 0;
    if (t < NBATCH * WR * NG) g_cnt2[t] = 0;
}

__global__ void k_geom() {
    int n = blockIdx.x * blockDim.x + threadIdx.x;
    if (n >= NB) return;
    int i = n >> 9;
    int j = n & 511;
    float y = (float)(((double)i * (-100.0)) / 511.0 + 50.0);
    float x = (float)(((double)j * (100.0)) / 511.0 + (-50.0));
    float rho = __fsqrt_rn(__fadd_rn(__fmul_rn(x, x), __fmul_rn(y, y)));
    float phi = atan2f(y, x);
    float theta_low = atan2f(-1.73f, rho);

    int row_low = row_from_theta(theta_low);

    float cv = __fmul_rn(__fdiv_rn(__fsub_rn(phi, phi_minf()), phi_rangef()), 2047.0f);
    cv = rintf(cv);
    cv = fminf(fmaxf(cv, 0.0f), 2047.0f);
    int col = (int)cv;

    int pos = atomicAdd(&g_cnt[col], 1);

    g_rho[n]    = rho;
    g_rowlow[n] = (unsigned char)row_low;
    g_colb[n]   = (unsigned short)col;
    if (pos < CAP) {
        g_cellof[col * CAP + pos] = n;
        g_slotp[n] = (unsigned short)pos;
    } else {
        g_slotp[n] = 0xFFFF;   // overflow: handled via direct-load items
    }
}

// per (b,cell): compute [rs,re], scatter items into intersecting buckets.
// Normal item: (slot<<6)|(lo<<3)|hi. Overflow item: FLAG|(cell<<6)|(lo<<3)|hi.
__global__ void k_rowhi(const int* __restrict__ zbin) {
    int idx = blockIdx.x * blockDim.x + threadIdx.x;
    if (idx >= NBATCH * NB) return;
    int n = idx & (NB - 1);
    int b = idx >> 18;
    int zb = zbin[idx];
    float zh = __fadd_rn(__fmul_rn((float)zb, (float)(6.0 / 30.0)),
                         (float)(-4.0 + (6.0 / 30.0) / 2.0));
    float theta_hi = atan2f(zh, g_rho[n]);
    int row_hi  = row_from_theta(theta_hi);
    int row_low = (int)g_rowlow[n];
    int rs = min(row_low, row_hi);
    int re = max(row_low, row_hi);
    int col  = (int)g_colb[n];
    unsigned p = g_slotp[n];
    unsigned payload = (p == 0xFFFFu) ? (FLAG_DIRECT | ((unsigned)n << 6))
                                      : (p << 6);
    int base = (b * WR + col) * NG;
    int g0 = rs >> 3, g1 = re >> 3;
    for (int g = g0; g <= g1; ++g) {
        int lo = max(rs - g * 8, 0);
        int hi = min(re - g * 8, 7);
        int pos = atomicAdd(&g_cnt2[base + g], 1);
        if (pos < CAP2)
            g_item[(size_t)(base + g) * CAP2 + pos] =
                payload | ((unsigned)lo << 3) | (unsigned)hi;
    }
}

// [B,C,N] -> [B,N,C]; 64x32 tile per CTA
__global__ void k_transpose(const float* __restrict__ src) {
    __shared__ float tA[32][33];
    __shared__ float tB[32][33];
    int b  = blockIdx.z;
    int n0 = blockIdx.x * 64;
    int c0 = blockIdx.y * 32;
    int tx = threadIdx.x;   // 0..7
    int ty = threadIdx.y;   // 0..31
    const float* row = &src[((size_t)(b * NC + c0 + ty)) * NB + n0 + tx * 4];
    float4 fa = *(const float4*)row;
    float4 fb = *(const float4*)(row + 32);
    tA[tx * 4 + 0][ty] = fa.x; tA[tx * 4 + 1][ty] = fa.y;
    tA[tx * 4 + 2][ty] = fa.z; tA[tx * 4 + 3][ty] = fa.w;
    tB[tx * 4 + 0][ty] = fb.x; tB[tx * 4 + 1][ty] = fb.y;
    tB[tx * 4 + 2][ty] = fb.z; tB[tx * 4 + 3][ty] = fb.w;
    __syncthreads();
    float4 wa, wb;
    wa.x = tA[ty][tx * 4 + 0]; wa.y = tA[ty][tx * 4 + 1];
    wa.z = tA[ty][tx * 4 + 2]; wa.w = tA[ty][tx * 4 + 3];
    wb.x = tB[ty][tx * 4 + 0]; wb.y = tB[ty][tx * 4 + 1];
    wb.z = tB[ty][tx * 4 + 2]; wb.w = tB[ty][tx * 4 + 3];
    *(float4*)&g_featT[((size_t)b * NB + (n0 + ty)) * NC + c0 + tx * 4]      = wa;
    *(float4*)&g_featT[((size_t)b * NB + (n0 + 32 + ty)) * NC + c0 + tx * 4] = wb;
}

// CTA = (col, b). Phase 1: stage column features into smem (one touch/cell).
// Phase 2: 8 warps = 8 row groups; lane owns 2 channels; acc in registers.
__global__ void __launch_bounds__(256) k_project() {
    extern __shared__ float feat_s[];        // CAP x 64 floats (80KB)
    int col = blockIdx.x;
    int b   = blockIdx.y;
    int t    = threadIdx.x;
    int g    = t >> 5;
    int lane = t & 31;

    int cnt = min(g_cnt[col], CAP);
    const float2* gfeat2 = (const float2*)g_featT + (size_t)b * NB * 32;

    // ---- phase 1: stage features, warp per cell row ----
    {
        float2* fs2 = (float2*)feat_s;
        const int* cells = g_cellof + col * CAP;
        for (int p = g; p < cnt; p += 8) {
            int cell = cells[p];                       // warp-uniform
            fs2[p * 32 + lane] = __ldg(&gfeat2[((size_t)cell << 5) + lane]);
        }
    }
    __syncthreads();

    // ---- phase 2: per-group interval max ----
    const float NF = -CUDART_INF_F;
    float2 a0 = make_float2(NF, NF);
    float2 a1 = a0, a2 = a0, a3 = a0, a4 = a0, a5 = a0, a6 = a0, a7 = a0;

    int bkt  = (b * WR + col) * NG + g;
    int cntg = min(g_cnt2[bkt], CAP2);
    const unsigned* items = g_item + (size_t)bkt * CAP2;
    const float2*   fs2   = (const float2*)feat_s;

    for (int i = 0; i < cntg; ++i) {
        unsigned it = __ldg(&items[i]);
        unsigned idx = (it >> 6) & 0x3FFFFu;
        int lo = (it >> 3) & 7;
        int hi = it & 7;
        float2 v;
        if (it & FLAG_DIRECT) {                        // rare overflow: global
            v = __ldg(&gfeat2[((size_t)idx << 5) + lane]);
        } else {
            v = fs2[idx * 32 + lane];
        }
        unsigned m = (0xFFu >> (7 - hi)) & (0xFFu << lo);
        if (m & 0x01u) { a0.x = fmaxf(a0.x, v.x); a0.y = fmaxf(a0.y, v.y); }
        if (m & 0x02u) { a1.x = fmaxf(a1.x, v.x); a1.y = fmaxf(a1.y, v.y); }
        if (m & 0x04u) { a2.x = fmaxf(a2.x, v.x); a2.y = fmaxf(a2.y, v.y); }
        if (m & 0x08u) { a3.x = fmaxf(a3.x, v.x); a3.y = fmaxf(a3.y, v.y); }
        if (m & 0x10u) { a4.x = fmaxf(a4.x, v.x); a4.y = fmaxf(a4.y, v.y); }
        if (m & 0x20u) { a5.x = fmaxf(a5.x, v.x); a5.y = fmaxf(a5.y, v.y); }
        if (m & 0x40u) { a6.x = fmaxf(a6.x, v.x); a6.y = fmaxf(a6.y, v.y); }
        if (m & 0x80u) { a7.x = fmaxf(a7.x, v.x); a7.y = fmaxf(a7.y, v.y); }
    }

    // ---- epilogue: scratch [b][col][r][c], coalesced ----
    float2* dst2 = (float2*)(g_scratch + (((size_t)(b * WR + col)) << 12)) + g * 8 * 32 + lane;
    dst2[0 * 32] = a0; dst2[1 * 32] = a1; dst2[2 * 32] = a2; dst2[3 * 32] = a3;
    dst2[4 * 32] = a4; dst2[5 * 32] = a5; dst2[6 * 32] = a6; dst2[7 * 32] = a7;
}

// scratch [b][col][r][c] -> out [b][c][r][col], -inf -> 0, both sides 128-bit
__global__ void k_final(float* __restrict__ out) {
    __shared__ float tile[32][33];
    int z = blockIdx.z;
    int b = z >> 6;
    int r = z & 63;
    int col0 = blockIdx.x * 32;
    int c0   = blockIdx.y * 32;
    int tx = threadIdx.x;   // 0..7
    int ty = threadIdx.y;   // 0..31
    float4 f = *(const float4*)&g_scratch[(((size_t)(b * WR + col0 + ty)) << 12)
                                          + (r << 6) + c0 + tx * 4];
    tile[tx * 4 + 0][ty] = f.x;
    tile[tx * 4 + 1][ty] = f.y;
    tile[tx * 4 + 2][ty] = f.z;
    tile[tx * 4 + 3][ty] = f.w;
    __syncthreads();
    float4 w;
    w.x = tile[ty][tx * 4 + 0];
    w.y = tile[ty][tx * 4 + 1];
    w.z = tile[ty][tx * 4 + 2];
    w.w = tile[ty][tx * 4 + 3];
    if (w.x == -CUDART_INF_F) w.x = 0.0f;
    if (w.y == -CUDART_INF_F) w.y = 0.0f;
    if (w.z == -CUDART_INF_F) w.z = 0.0f;
    if (w.w == -CUDART_INF_F) w.w = 0.0f;
    *(float4*)&out[(((size_t)(b * NC + c0 + ty)) * HR + r) * WR + col0 + tx * 4] = w;
}

extern "C" void kernel_launch(void* const* d_in, const int* in_sizes, int n_in,
                              void* d_out, int out_size) {
    const float* feat = (const float*)d_in[0];   // [2,64,512,512] f32
    const int*   zbin = (const int*)d_in[1];     // [2,1,512,512] i32
    float*       out  = (float*)d_out;           // [2,64,64,2048] f32

    cudaFuncSetAttribute(k_project, cudaFuncAttributeMaxDynamicSharedMemorySize,
                         SMEM_FEAT);

    k_zero<<<(NBATCH * WR * NG + 255) / 256, 256>>>();
    k_geom<<<NB / 256, 256>>>();
    k_rowhi<<<(NBATCH * NB) / 256, 256>>>(zbin);
    k_transpose<<<dim3(NB / 64, NC / 32, NBATCH), dim3(8, 32)>>>(feat);
    k_project<<<dim3(WR, NBATCH), 256, SMEM_FEAT>>>();
    k_final<<<dim3(WR / 32, NC / 32, NBATCH * HR), dim3(8, 32)>>>(out);
}

// round 10
// speedup vs baseline: 1.3995x; 1.3995x over previous
#include <cuda_runtime.h>
#include <cuda_bf16.h>
#include <math.h>
#include <math_constants.h>

#define HB 512
#define WB 512
#define NB (HB*WB)          // 262144 BEV cells
#define NC 64               // channels
#define NBATCH 2
#define HR 64
#define WR 2048
#define NG 8                // row groups (8 rows each)
#define CAP2 512            // bucket capacity per (col,group)
#define ITEM_PAD 0x38u      // lo=7,hi=0 -> empty mask, cell=0

// device scratch
__device__ float          g_rho[NB];
__device__ unsigned char  g_rowlow[NB];
__device__ unsigned short g_colb[NB];
__device__ int            g_cnt2[NBATCH * WR * NG];
__device__ unsigned int   g_item[(size_t)NBATCH * WR * NG * CAP2]; // (cell<<6)|(lo<<3)|hi
__device__ float          g_featT[(size_t)NBATCH * NB * NC];        // [B][N][C]
__device__ float          g_scratch[(size_t)NBATCH * WR * HR * NC]; // [B][col][r][c]

__device__ __forceinline__ float th_maxf()   { return (float)(3.0 * (CUDART_PI / 180.0)); }
__device__ __forceinline__ float th_rangef() {
    double tmax = 3.0 * (CUDART_PI / 180.0);
    double tmin = -25.0 * (CUDART_PI / 180.0);
    return (float)(tmax - tmin);
}
__device__ __forceinline__ float phi_minf()   { return (float)(-CUDART_PI); }
__device__ __forceinline__ float phi_rangef() { return (float)(2.0 * CUDART_PI); }

__device__ __forceinline__ int row_from_theta(float theta) {
    float v = __fmul_rn(__fdiv_rn(__fsub_rn(th_maxf(), theta), th_rangef()), 63.0f);
    v = rintf(v);
    v = fminf(fmaxf(v, 0.0f), 63.0f);
    return (int)v;
}

// ---------------- kernels ----------------
__global__ void k_zero() {
    int t = blockIdx.x * blockDim.x + threadIdx.x;
    if (t < NBATCH * WR * NG) g_cnt2[t] = 0;
}

__global__ void k_geom() {
    int n = blockIdx.x * blockDim.x + threadIdx.x;
    if (n >= NB) return;
    int i = n >> 9;
    int j = n & 511;
    float y = (float)(((double)i * (-100.0)) / 511.0 + 50.0);
    float x = (float)(((double)j * (100.0)) / 511.0 + (-50.0));
    float rho = __fsqrt_rn(__fadd_rn(__fmul_rn(x, x), __fmul_rn(y, y)));
    float phi = atan2f(y, x);
    float theta_low = atan2f(-1.73f, rho);

    int row_low = row_from_theta(theta_low);

    float cv = __fmul_rn(__fdiv_rn(__fsub_rn(phi, phi_minf()), phi_rangef()), 2047.0f);
    cv = rintf(cv);
    cv = fminf(fmaxf(cv, 0.0f), 2047.0f);
    int col = (int)cv;

    g_rho[n]    = rho;
    g_rowlow[n] = (unsigned char)row_low;
    g_colb[n]   = (unsigned short)col;
}

// per (b,cell): compute [rs,re], scatter (cell,lo,hi) into intersecting buckets
__global__ void k_rowhi(const int* __restrict__ zbin) {
    int idx = blockIdx.x * blockDim.x + threadIdx.x;
    if (idx >= NBATCH * NB) return;
    int n = idx & (NB - 1);
    int b = idx >> 18;
    int zb = zbin[idx];
    float zh = __fadd_rn(__fmul_rn((float)zb, (float)(6.0 / 30.0)),
                         (float)(-4.0 + (6.0 / 30.0) / 2.0));
    float theta_hi = atan2f(zh, g_rho[n]);
    int row_hi  = row_from_theta(theta_hi);
    int row_low = (int)g_rowlow[n];
    int rs = min(row_low, row_hi);
    int re = max(row_low, row_hi);
    int col  = (int)g_colb[n];
    int base = (b * WR + col) * NG;
    int g0 = rs >> 3, g1 = re >> 3;
    for (int g = g0; g <= g1; ++g) {
        int lo = max(rs - g * 8, 0);
        int hi = min(re - g * 8, 7);
        int pos = atomicAdd(&g_cnt2[base + g], 1);
        if (pos < CAP2)
            g_item[(size_t)(base + g) * CAP2 + pos] =
                ((unsigned)n << 6) | ((unsigned)lo << 3) | (unsigned)hi;
    }
}

// [B,C,N] -> [B,N,C]; 64x32 tile per CTA
__global__ void k_transpose(const float* __restrict__ src) {
    __shared__ float tA[32][33];
    __shared__ float tB[32][33];
    int b  = blockIdx.z;
    int n0 = blockIdx.x * 64;
    int c0 = blockIdx.y * 32;
    int tx = threadIdx.x;   // 0..7
    int ty = threadIdx.y;   // 0..31
    const float* row = &src[((size_t)(b * NC + c0 + ty)) * NB + n0 + tx * 4];
    float4 fa = *(const float4*)row;
    float4 fb = *(const float4*)(row + 32);
    tA[tx * 4 + 0][ty] = fa.x; tA[tx * 4 + 1][ty] = fa.y;
    tA[tx * 4 + 2][ty] = fa.z; tA[tx * 4 + 3][ty] = fa.w;
    tB[tx * 4 + 0][ty] = fb.x; tB[tx * 4 + 1][ty] = fb.y;
    tB[tx * 4 + 2][ty] = fb.z; tB[tx * 4 + 3][ty] = fb.w;
    __syncthreads();
    float4 wa, wb;
    wa.x = tA[ty][tx * 4 + 0]; wa.y = tA[ty][tx * 4 + 1];
    wa.z = tA[ty][tx * 4 + 2]; wa.w = tA[ty][tx * 4 + 3];
    wb.x = tB[ty][tx * 4 + 0]; wb.y = tB[ty][tx * 4 + 1];
    wb.z = tB[ty][tx * 4 + 2]; wb.w = tB[ty][tx * 4 + 3];
    *(float4*)&g_featT[((size_t)b * NB + (n0 + ty)) * NC + c0 + tx * 4]      = wa;
    *(float4*)&g_featT[((size_t)b * NB + (n0 + 32 + ty)) * NC + c0 + tx * 4] = wb;
}

// CTA = (col, b). 8 warps = 8 row groups; lane owns 2 channels; acc in regs.
// Feature loads pipelined 8 deep (two double-buffered blocks of 4).
__global__ void __launch_bounds__(256) k_project() {
    int col = blockIdx.x;
    int b   = blockIdx.y;
    int t    = threadIdx.x;
    int g    = t >> 5;
    int lane = t & 31;

    const float NF = -CUDART_INF_F;
    float2 a0 = make_float2(NF, NF);
    float2 a1 = a0, a2 = a0, a3 = a0, a4 = a0, a5 = a0, a6 = a0, a7 = a0;

    int bkt  = (b * WR + col) * NG + g;
    int cntg = min(g_cnt2[bkt], CAP2);
    const unsigned* items  = g_item + (size_t)bkt * CAP2;
    const float2*   featT2 = (const float2*)g_featT + (size_t)b * NB * 32;

    unsigned itA[4], itB[4];
    float2   vA[4],  vB[4];

#define UPDATE(IT, V) do {                                                     \
        unsigned _it = (IT);                                                   \
        int _lo = (_it >> 3) & 7;                                              \
        int _hi = _it & 7;                                                     \
        unsigned _m = (0xFFu >> (7 - _hi)) & (0xFFu << _lo);                   \
        float2 _v = (V);                                                       \
        if (_m & 0x01u) { a0.x = fmaxf(a0.x, _v.x); a0.y = fmaxf(a0.y, _v.y); }\
        if (_m & 0x02u) { a1.x = fmaxf(a1.x, _v.x); a1.y = fmaxf(a1.y, _v.y); }\
        if (_m & 0x04u) { a2.x = fmaxf(a2.x, _v.x); a2.y = fmaxf(a2.y, _v.y); }\
        if (_m & 0x08u) { a3.x = fmaxf(a3.x, _v.x); a3.y = fmaxf(a3.y, _v.y); }\
        if (_m & 0x10u) { a4.x = fmaxf(a4.x, _v.x); a4.y = fmaxf(a4.y, _v.y); }\
        if (_m & 0x20u) { a5.x = fmaxf(a5.x, _v.x); a5.y = fmaxf(a5.y, _v.y); }\
        if (_m & 0x40u) { a6.x = fmaxf(a6.x, _v.x); a6.y = fmaxf(a6.y, _v.y); }\
        if (_m & 0x80u) { a7.x = fmaxf(a7.x, _v.x); a7.y = fmaxf(a7.y, _v.y); }\
    } while (0)

    // prologue: block A <- [0,4)
    #pragma unroll
    for (int k = 0; k < 4; ++k) {
        itA[k] = ITEM_PAD;
        if (k < cntg) {
            itA[k] = __ldg(&items[k]);
            vA[k]  = __ldg(&featT2[((size_t)(itA[k] >> 6) << 5) + lane]);
        }
    }
    for (int base = 0; base < cntg; base += 8) {
        // load block B <- [base+4, base+8)
        #pragma unroll
        for (int k = 0; k < 4; ++k) {
            int j = base + 4 + k;
            itB[k] = ITEM_PAD;
            if (j < cntg) {
                itB[k] = __ldg(&items[j]);
                vB[k]  = __ldg(&featT2[((size_t)(itB[k] >> 6) << 5) + lane]);
            }
        }
        // process block A
        #pragma unroll
        for (int k = 0; k < 4; ++k) UPDATE(itA[k], vA[k]);
        // load block A <- [base+8, base+12)
        #pragma unroll
        for (int k = 0; k < 4; ++k) {
            int j = base + 8 + k;
            itA[k] = ITEM_PAD;
            if (j < cntg) {
                itA[k] = __ldg(&items[j]);
                vA[k]  = __ldg(&featT2[((size_t)(itA[k] >> 6) << 5) + lane]);
            }
        }
        // process block B
        #pragma unroll
        for (int k = 0; k < 4; ++k) UPDATE(itB[k], vB[k]);
    }
#undef UPDATE

    // epilogue: scratch [b][col][r][c], coalesced
    float2* dst2 = (float2*)(g_scratch + (((size_t)(b * WR + col)) << 12)) + g * 8 * 32 + lane;
    dst2[0 * 32] = a0; dst2[1 * 32] = a1; dst2[2 * 32] = a2; dst2[3 * 32] = a3;
    dst2[4 * 32] = a4; dst2[5 * 32] = a5; dst2[6 * 32] = a6; dst2[7 * 32] = a7;
}

// scratch [b][col][r][c] -> out [b][c][r][col], -inf -> 0, both sides 128-bit
__global__ void k_final(float* __restrict__ out) {
    __shared__ float tile[32][33];
    int z = blockIdx.z;
    int b = z >> 6;
    int r = z & 63;
    int col0 = blockIdx.x * 32;
    int c0   = blockIdx.y * 32;
    int tx = threadIdx.x;   // 0..7
    int ty = threadIdx.y;   // 0..31
    float4 f = *(const float4*)&g_scratch[(((size_t)(b * WR + col0 + ty)) << 12)
                                          + (r << 6) + c0 + tx * 4];
    tile[tx * 4 + 0][ty] = f.x;
    tile[tx * 4 + 1][ty] = f.y;
    tile[tx * 4 + 2][ty] = f.z;
    tile[tx * 4 + 3][ty] = f.w;
    __syncthreads();
    float4 w;
    w.x = tile[ty][tx * 4 + 0];
    w.y = tile[ty][tx * 4 + 1];
    w.z = tile[ty][tx * 4 + 2];
    w.w = tile[ty][tx * 4 + 3];
    if (w.x == -CUDART_INF_F) w.x = 0.0f;
    if (w.y == -CUDART_INF_F) w.y = 0.0f;
    if (w.z == -CUDART_INF_F) w.z = 0.0f;
    if (w.w == -CUDART_INF_F) w.w = 0.0f;
    *(float4*)&out[(((size_t)(b * NC + c0 + ty)) * HR + r) * WR + col0 + tx * 4] = w;
}

extern "C" void kernel_launch(void* const* d_in, const int* in_sizes, int n_in,
                              void* d_out, int out_size) {
    const float* feat = (const float*)d_in[0];   // [2,64,512,512] f32
    const int*   zbin = (const int*)d_in[1];     // [2,1,512,512] i32
    float*       out  = (float*)d_out;           // [2,64,64,2048] f32

    k_zero<<<(NBATCH * WR * NG + 255) / 256, 256>>>();
    k_geom<<<NB / 256, 256>>>();
    k_rowhi<<<(NBATCH * NB) / 256, 256>>>(zbin);
    k_transpose<<<dim3(NB / 64, NC / 32, NBATCH), dim3(8, 32)>>>(feat);
    k_project<<<dim3(WR, NBATCH), 256>>>();
    k_final<<<dim3(WR / 32, NC / 32, NBATCH * HR), dim3(8, 32)>>>(out);
}

// round 11
// speedup vs baseline: 1.7529x; 1.2525x over previous
#include <cuda_runtime.h>
#include <cuda_bf16.h>
#include <math.h>
#include <math_constants.h>

#define HB 512
#define WB 512
#define NB (HB*WB)          // 262144 BEV cells
#define NC 64               // channels
#define NBATCH 2
#define HR 64
#define WR 2048
#define NG 8                // row groups (8 rows each)
#define CAP2 512            // bucket capacity per (col,group)
#define ITEM_PAD 0x38u      // lo=7,hi=0 -> empty mask, cell=0

// device scratch
__device__ float          g_rho[NB];
__device__ unsigned char  g_rowlow[NB];
__device__ unsigned short g_colb[NB];
__device__ int            g_cnt2[NBATCH * WR * NG];
__device__ unsigned int   g_item[(size_t)NBATCH * WR * NG * CAP2]; // (cell<<6)|(lo<<3)|hi
__device__ float          g_featT[(size_t)NBATCH * NB * NC];        // [B][N][C]
__device__ float          g_scratch[(size_t)NBATCH * WR * HR * NC]; // [B][col][r][c]

__device__ __forceinline__ float th_maxf()   { return (float)(3.0 * (CUDART_PI / 180.0)); }
__device__ __forceinline__ float th_rangef() {
    double tmax = 3.0 * (CUDART_PI / 180.0);
    double tmin = -25.0 * (CUDART_PI / 180.0);
    return (float)(tmax - tmin);
}
__device__ __forceinline__ float phi_minf()   { return (float)(-CUDART_PI); }
__device__ __forceinline__ float phi_rangef() { return (float)(2.0 * CUDART_PI); }

__device__ __forceinline__ int row_from_theta(float theta) {
    float v = __fmul_rn(__fdiv_rn(__fsub_rn(th_maxf(), theta), th_rangef()), 63.0f);
    v = rintf(v);
    v = fminf(fmaxf(v, 0.0f), 63.0f);
    return (int)v;
}

// ---------------- kernels ----------------
// geometry + zeroing of bucket counters (first 32768 threads)
__global__ void k_geom() {
    int n = blockIdx.x * blockDim.x + threadIdx.x;
    if (n < NBATCH * WR * NG) g_cnt2[n] = 0;
    if (n >= NB) return;
    int i = n >> 9;
    int j = n & 511;
    float y = (float)(((double)i * (-100.0)) / 511.0 + 50.0);
    float x = (float)(((double)j * (100.0)) / 511.0 + (-50.0));
    float rho = __fsqrt_rn(__fadd_rn(__fmul_rn(x, x), __fmul_rn(y, y)));
    float phi = atan2f(y, x);
    float theta_low = atan2f(-1.73f, rho);

    int row_low = row_from_theta(theta_low);

    float cv = __fmul_rn(__fdiv_rn(__fsub_rn(phi, phi_minf()), phi_rangef()), 2047.0f);
    cv = rintf(cv);
    cv = fminf(fmaxf(cv, 0.0f), 2047.0f);
    int col = (int)cv;

    g_rho[n]    = rho;
    g_rowlow[n] = (unsigned char)row_low;
    g_colb[n]   = (unsigned short)col;
}

// per (b,cell): compute [rs,re], scatter (cell,lo,hi) into intersecting buckets
__global__ void k_rowhi(const int* __restrict__ zbin) {
    int idx = blockIdx.x * blockDim.x + threadIdx.x;
    if (idx >= NBATCH * NB) return;
    int n = idx & (NB - 1);
    int b = idx >> 18;
    int zb = zbin[idx];
    float zh = __fadd_rn(__fmul_rn((float)zb, (float)(6.0 / 30.0)),
                         (float)(-4.0 + (6.0 / 30.0) / 2.0));
    float theta_hi = atan2f(zh, g_rho[n]);
    int row_hi  = row_from_theta(theta_hi);
    int row_low = (int)g_rowlow[n];
    int rs = min(row_low, row_hi);
    int re = max(row_low, row_hi);
    int col  = (int)g_colb[n];
    int base = (b * WR + col) * NG;
    int g0 = rs >> 3, g1 = re >> 3;
    for (int g = g0; g <= g1; ++g) {
        int lo = max(rs - g * 8, 0);
        int hi = min(re - g * 8, 7);
        int pos = atomicAdd(&g_cnt2[base + g], 1);
        if (pos < CAP2)
            g_item[(size_t)(base + g) * CAP2 + pos] =
                ((unsigned)n << 6) | ((unsigned)lo << 3) | (unsigned)hi;
    }
}

// [B,C,N] -> [B,N,C]; 64x32 tile per CTA
__global__ void k_transpose(const float* __restrict__ src) {
    __shared__ float tA[32][33];
    __shared__ float tB[32][33];
    int b  = blockIdx.z;
    int n0 = blockIdx.x * 64;
    int c0 = blockIdx.y * 32;
    int tx = threadIdx.x;   // 0..7
    int ty = threadIdx.y;   // 0..31
    const float* row = &src[((size_t)(b * NC + c0 + ty)) * NB + n0 + tx * 4];
    float4 fa = *(const float4*)row;
    float4 fb = *(const float4*)(row + 32);
    tA[tx * 4 + 0][ty] = fa.x; tA[tx * 4 + 1][ty] = fa.y;
    tA[tx * 4 + 2][ty] = fa.z; tA[tx * 4 + 3][ty] = fa.w;
    tB[tx * 4 + 0][ty] = fb.x; tB[tx * 4 + 1][ty] = fb.y;
    tB[tx * 4 + 2][ty] = fb.z; tB[tx * 4 + 3][ty] = fb.w;
    __syncthreads();
    float4 wa, wb;
    wa.x = tA[ty][tx * 4 + 0]; wa.y = tA[ty][tx * 4 + 1];
    wa.z = tA[ty][tx * 4 + 2]; wa.w = tA[ty][tx * 4 + 3];
    wb.x = tB[ty][tx * 4 + 0]; wb.y = tB[ty][tx * 4 + 1];
    wb.z = tB[ty][tx * 4 + 2]; wb.w = tB[ty][tx * 4 + 3];
    *(float4*)&g_featT[((size_t)b * NB + (n0 + ty)) * NC + c0 + tx * 4]      = wa;
    *(float4*)&g_featT[((size_t)b * NB + (n0 + 32 + ty)) * NC + c0 + tx * 4] = wb;
}

// CTA = (col, b, gpair): 64 threads = 2 warps = 2 row groups (fine-grained
// for load balance under bucket skew). Lane owns 2 channels; acc in regs.
// Feature loads pipelined 8 deep (two double-buffered blocks of 4).
__global__ void __launch_bounds__(64) k_project() {
    int col = blockIdx.x;
    int b   = blockIdx.y;
    int g    = blockIdx.z * 2 + (threadIdx.x >> 5);
    int lane = threadIdx.x & 31;

    const float NF = -CUDART_INF_F;
    float2 a0 = make_float2(NF, NF);
    float2 a1 = a0, a2 = a0, a3 = a0, a4 = a0, a5 = a0, a6 = a0, a7 = a0;

    int bkt  = (b * WR + col) * NG + g;
    int cntg = min(g_cnt2[bkt], CAP2);
    const unsigned* items  = g_item + (size_t)bkt * CAP2;
    const float2*   featT2 = (const float2*)g_featT + (size_t)b * NB * 32;

    unsigned itA[4], itB[4];
    float2   vA[4],  vB[4];

#define UPDATE(IT, V) do {                                                     \
        unsigned _it = (IT);                                                   \
        int _lo = (_it >> 3) & 7;                                              \
        int _hi = _it & 7;                                                     \
        unsigned _m = (0xFFu >> (7 - _hi)) & (0xFFu << _lo);                   \
        float2 _v = (V);                                                       \
        if (_m & 0x01u) { a0.x = fmaxf(a0.x, _v.x); a0.y = fmaxf(a0.y, _v.y); }\
        if (_m & 0x02u) { a1.x = fmaxf(a1.x, _v.x); a1.y = fmaxf(a1.y, _v.y); }\
        if (_m & 0x04u) { a2.x = fmaxf(a2.x, _v.x); a2.y = fmaxf(a2.y, _v.y); }\
        if (_m & 0x08u) { a3.x = fmaxf(a3.x, _v.x); a3.y = fmaxf(a3.y, _v.y); }\
        if (_m & 0x10u) { a4.x = fmaxf(a4.x, _v.x); a4.y = fmaxf(a4.y, _v.y); }\
        if (_m & 0x20u) { a5.x = fmaxf(a5.x, _v.x); a5.y = fmaxf(a5.y, _v.y); }\
        if (_m & 0x40u) { a6.x = fmaxf(a6.x, _v.x); a6.y = fmaxf(a6.y, _v.y); }\
        if (_m & 0x80u) { a7.x = fmaxf(a7.x, _v.x); a7.y = fmaxf(a7.y, _v.y); }\
    } while (0)

    // prologue: block A <- [0,4)
    #pragma unroll
    for (int k = 0; k < 4; ++k) {
        itA[k] = ITEM_PAD;
        if (k < cntg) {
            itA[k] = __ldg(&items[k]);
            vA[k]  = __ldg(&featT2[((size_t)(itA[k] >> 6) << 5) + lane]);
        }
    }
    for (int base = 0; base < cntg; base += 8) {
        // load block B <- [base+4, base+8)
        #pragma unroll
        for (int k = 0; k < 4; ++k) {
            int j = base + 4 + k;
            itB[k] = ITEM_PAD;
            if (j < cntg) {
                itB[k] = __ldg(&items[j]);
                vB[k]  = __ldg(&featT2[((size_t)(itB[k] >> 6) << 5) + lane]);
            }
        }
        // process block A
        #pragma unroll
        for (int k = 0; k < 4; ++k) UPDATE(itA[k], vA[k]);
        // load block A <- [base+8, base+12)
        #pragma unroll
        for (int k = 0; k < 4; ++k) {
            int j = base + 8 + k;
            itA[k] = ITEM_PAD;
            if (j < cntg) {
                itA[k] = __ldg(&items[j]);
                vA[k]  = __ldg(&featT2[((size_t)(itA[k] >> 6) << 5) + lane]);
            }
        }
        // process block B
        #pragma unroll
        for (int k = 0; k < 4; ++k) UPDATE(itB[k], vB[k]);
    }
#undef UPDATE

    // epilogue: scratch [b][col][r][c], coalesced
    float2* dst2 = (float2*)(g_scratch + (((size_t)(b * WR + col)) << 12)) + g * 8 * 32 + lane;
    dst2[0 * 32] = a0; dst2[1 * 32] = a1; dst2[2 * 32] = a2; dst2[3 * 32] = a3;
    dst2[4 * 32] = a4; dst2[5 * 32] = a5; dst2[6 * 32] = a6; dst2[7 * 32] = a7;
}

// scratch [b][col][r][c] -> out [b][c][r][col], -inf -> 0, both sides 128-bit
__global__ void k_final(float* __restrict__ out) {
    __shared__ float tile[32][33];
    int z = blockIdx.z;
    int b = z >> 6;
    int r = z & 63;
    int col0 = blockIdx.x * 32;
    int c0   = blockIdx.y * 32;
    int tx = threadIdx.x;   // 0..7
    int ty = threadIdx.y;   // 0..31
    float4 f = *(const float4*)&g_scratch[(((size_t)(b * WR + col0 + ty)) << 12)
                                          + (r << 6) + c0 + tx * 4];
    tile[tx * 4 + 0][ty] = f.x;
    tile[tx * 4 + 1][ty] = f.y;
    tile[tx * 4 + 2][ty] = f.z;
    tile[tx * 4 + 3][ty] = f.w;
    __syncthreads();
    float4 w;
    w.x = tile[ty][tx * 4 + 0];
    w.y = tile[ty][tx * 4 + 1];
    w.z = tile[ty][tx * 4 + 2];
    w.w = tile[ty][tx * 4 + 3];
    if (w.x == -CUDART_INF_F) w.x = 0.0f;
    if (w.y == -CUDART_INF_F) w.y = 0.0f;
    if (w.z == -CUDART_INF_F) w.z = 0.0f;
    if (w.w == -CUDART_INF_F) w.w = 0.0f;
    *(float4*)&out[(((size_t)(b * NC + c0 + ty)) * HR + r) * WR + col0 + tx * 4] = w;
}

extern "C" void kernel_launch(void* const* d_in, const int* in_sizes, int n_in,
                              void* d_out, int out_size) {
    const float* feat = (const float*)d_in[0];   // [2,64,512,512] f32
    const int*   zbin = (const int*)d_in[1];     // [2,1,512,512] i32
    float*       out  = (float*)d_out;           // [2,64,64,2048] f32

    k_geom<<<NB / 256, 256>>>();
    k_rowhi<<<(NBATCH * NB) / 256, 256>>>(zbin);
    k_transpose<<<dim3(NB / 64, NC / 32, NBATCH), dim3(8, 32)>>>(feat);
    k_project<<<dim3(WR, NBATCH, NG / 2), 64>>>();
    k_final<<<dim3(WR / 32, NC / 32, NBATCH * HR), dim3(8, 32)>>>(out);
}

// round 13
// speedup vs baseline: 1.8739x; 1.0690x over previous
#include <cuda_runtime.h>
#include <cuda_bf16.h>
#include <math.h>
#include <math_constants.h>

#define HB 512
#define WB 512
#define NB (HB*WB)          // 262144 BEV cells
#define NC 64               // channels
#define NBATCH 2
#define HR 64
#define WR 2048
#define NG 8                // row groups (8 rows each)
#define CAP2 512            // bucket capacity per (col,group)

// device scratch
__device__ float          g_rho[NB];
__device__ unsigned char  g_rowlow[NB];
__device__ unsigned short g_colb[NB];
__device__ int            g_cnt2[NBATCH * WR * NG];
__device__ unsigned int   g_item[(size_t)NBATCH * WR * NG * CAP2]; // (cell<<8)|mask8
__device__ float          g_featT[(size_t)NBATCH * NB * NC];        // [B][N][C]
__device__ float          g_scratch[(size_t)NBATCH * WR * HR * NC]; // [B][col][r][c]

__device__ __forceinline__ float th_maxf()   { return (float)(3.0 * (CUDART_PI / 180.0)); }
__device__ __forceinline__ float th_rangef() {
    double tmax = 3.0 * (CUDART_PI / 180.0);
    double tmin = -25.0 * (CUDART_PI / 180.0);
    return (float)(tmax - tmin);
}
__device__ __forceinline__ float phi_minf()   { return (float)(-CUDART_PI); }
__device__ __forceinline__ float phi_rangef() { return (float)(2.0 * CUDART_PI); }

__device__ __forceinline__ int row_from_theta(float theta) {
    float v = __fmul_rn(__fdiv_rn(__fsub_rn(th_maxf(), theta), th_rangef()), 63.0f);
    v = rintf(v);
    v = fminf(fmaxf(v, 0.0f), 63.0f);
    return (int)v;
}

// ---------------- kernels ----------------
// geometry + zeroing of bucket counters (first 32768 threads)
__global__ void k_geom() {
    int n = blockIdx.x * blockDim.x + threadIdx.x;
    if (n < NBATCH * WR * NG) g_cnt2[n] = 0;
    if (n >= NB) return;
    int i = n >> 9;
    int j = n & 511;
    float y = (float)(((double)i * (-100.0)) / 511.0 + 50.0);
    float x = (float)(((double)j * (100.0)) / 511.0 + (-50.0));
    float rho = __fsqrt_rn(__fadd_rn(__fmul_rn(x, x), __fmul_rn(y, y)));
    float phi = atan2f(y, x);
    float theta_low = atan2f(-1.73f, rho);

    int row_low = row_from_theta(theta_low);

    float cv = __fmul_rn(__fdiv_rn(__fsub_rn(phi, phi_minf()), phi_rangef()), 2047.0f);
    cv = rintf(cv);
    cv = fminf(fmaxf(cv, 0.0f), 2047.0f);
    int col = (int)cv;

    g_rho[n]    = rho;
    g_rowlow[n] = (unsigned char)row_low;
    g_colb[n]   = (unsigned short)col;
}

// per (b,cell): compute [rs,re], scatter (cell<<8 | rowmask) into buckets
__global__ void k_rowhi(const int* __restrict__ zbin) {
    int idx = blockIdx.x * blockDim.x + threadIdx.x;
    if (idx >= NBATCH * NB) return;
    int n = idx & (NB - 1);
    int b = idx >> 18;
    int zb = zbin[idx];
    float zh = __fadd_rn(__fmul_rn((float)zb, (float)(6.0 / 30.0)),
                         (float)(-4.0 + (6.0 / 30.0) / 2.0));
    float theta_hi = atan2f(zh, g_rho[n]);
    int row_hi  = row_from_theta(theta_hi);
    int row_low = (int)g_rowlow[n];
    int rs = min(row_low, row_hi);
    int re = max(row_low, row_hi);
    int col  = (int)g_colb[n];
    int base = (b * WR + col) * NG;
    int g0 = rs >> 3, g1 = re >> 3;
    unsigned cellhi = (unsigned)n << 8;
    for (int g = g0; g <= g1; ++g) {
        int lo = max(rs - g * 8, 0);
        int hi = min(re - g * 8, 7);
        unsigned mask = (0xFFu >> (7 - hi)) & (0xFFu << lo);
        int pos = atomicAdd(&g_cnt2[base + g], 1);
        if (pos < CAP2)
            g_item[(size_t)(base + g) * CAP2 + pos] = cellhi | mask;
    }
}

// [B,C,N] -> [B,N,C]; 64x32 tile per CTA
__global__ void k_transpose(const float* __restrict__ src) {
    __shared__ float tA[32][33];
    __shared__ float tB[32][33];
    int b  = blockIdx.z;
    int n0 = blockIdx.x * 64;
    int c0 = blockIdx.y * 32;
    int tx = threadIdx.x;   // 0..7
    int ty = threadIdx.y;   // 0..31
    const float* row = &src[((size_t)(b * NC + c0 + ty)) * NB + n0 + tx * 4];
    float4 fa = *(const float4*)row;
    float4 fb = *(const float4*)(row + 32);
    tA[tx * 4 + 0][ty] = fa.x; tA[tx * 4 + 1][ty] = fa.y;
    tA[tx * 4 + 2][ty] = fa.z; tA[tx * 4 + 3][ty] = fa.w;
    tB[tx * 4 + 0][ty] = fb.x; tB[tx * 4 + 1][ty] = fb.y;
    tB[tx * 4 + 2][ty] = fb.z; tB[tx * 4 + 3][ty] = fb.w;
    __syncthreads();
    float4 wa, wb;
    wa.x = tA[ty][tx * 4 + 0]; wa.y = tA[ty][tx * 4 + 1];
    wa.z = tA[ty][tx * 4 + 2]; wa.w = tA[ty][tx * 4 + 3];
    wb.x = tB[ty][tx * 4 + 0]; wb.y = tB[ty][tx * 4 + 1];
    wb.z = tB[ty][tx * 4 + 2]; wb.w = tB[ty][tx * 4 + 3];
    *(float4*)&g_featT[((size_t)b * NB + (n0 + ty)) * NC + c0 + tx * 4]      = wa;
    *(float4*)&g_featT[((size_t)b * NB + (n0 + 32 + ty)) * NC + c0 + tx * 4] = wb;
}

// CTA = (colperm, b, gpair): 64 threads = 2 warps = 2 row groups.
// Lane owns 2 channels; acc in regs. item = (cell<<8)|mask; cell<<8 doubles
// as the feature-row byte offset (256 B/row). Loads pipelined 8 deep.
__global__ void __launch_bounds__(64) k_project() {
    int col = (blockIdx.x * 331) & (WR - 1);   // spread heavy columns
    int b   = blockIdx.y;
    int g    = blockIdx.z * 2 + (threadIdx.x >> 5);
    int lane = threadIdx.x & 31;

    const float NF = -CUDART_INF_F;
    float2 a0 = make_float2(NF, NF);
    float2 a1 = a0, a2 = a0, a3 = a0, a4 = a0, a5 = a0, a6 = a0, a7 = a0;

    int bkt  = (b * WR + col) * NG + g;
    int cntg = min(g_cnt2[bkt], CAP2);
    const unsigned* items = g_item + (size_t)bkt * CAP2;
    // per-lane feature base: batch offset + this lane's channel pair
    const char* featc = (const char*)g_featT + ((size_t)b * NB * NC + lane * 2) * 4;

    unsigned itA[4], itB[4];
    float2   vA[4],  vB[4];

#define FLOAD(IT) (*(const float2*)(featc + (size_t)((IT) & 0xFFFFFF00u)))
#define UPDATE(IT, V) do {                                                     \
        unsigned _m = (IT) & 0xFFu;                                            \
        float2 _v = (V);                                                       \
        if (_m & 0x01u) { a0.x = fmaxf(a0.x, _v.x); a0.y = fmaxf(a0.y, _v.y); }\
        if (_m & 0x02u) { a1.x = fmaxf(a1.x, _v.x); a1.y = fmaxf(a1.y, _v.y); }\
        if (_m & 0x04u) { a2.x = fmaxf(a2.x, _v.x); a2.y = fmaxf(a2.y, _v.y); }\
        if (_m & 0x08u) { a3.x = fmaxf(a3.x, _v.x); a3.y = fmaxf(a3.y, _v.y); }\
        if (_m & 0x10u) { a4.x = fmaxf(a4.x, _v.x); a4.y = fmaxf(a4.y, _v.y); }\
        if (_m & 0x20u) { a5.x = fmaxf(a5.x, _v.x); a5.y = fmaxf(a5.y, _v.y); }\
        if (_m & 0x40u) { a6.x = fmaxf(a6.x, _v.x); a6.y = fmaxf(a6.y, _v.y); }\
        if (_m & 0x80u) { a7.x = fmaxf(a7.x, _v.x); a7.y = fmaxf(a7.y, _v.y); }\
    } while (0)

    // prologue: block A <- [0,4)
    #pragma unroll
    for (int k = 0; k < 4; ++k) {
        itA[k] = 0u;                       // mask 0 -> no update
        if (k < cntg) {
            itA[k] = __ldg(&items[k]);
            vA[k]  = FLOAD(itA[k]);
        }
    }
    for (int base = 0; base < cntg; base += 8) {
        #pragma unroll
        for (int k = 0; k < 4; ++k) {
            int j = base + 4 + k;
            itB[k] = 0u;
            if (j < cntg) {
                itB[k] = __ldg(&items[j]);
                vB[k]  = FLOAD(itB[k]);
            }
        }
        #pragma unroll
        for (int k = 0; k < 4; ++k) UPDATE(itA[k], vA[k]);
        #pragma unroll
        for (int k = 0; k < 4; ++k) {
            int j = base + 8 + k;
            itA[k] = 0u;
            if (j < cntg) {
                itA[k] = __ldg(&items[j]);
                vA[k]  = FLOAD(itA[k]);
            }
        }
        #pragma unroll
        for (int k = 0; k < 4; ++k) UPDATE(itB[k], vB[k]);
    }
#undef UPDATE
#undef FLOAD

    // epilogue: scratch [b][col][r][c], coalesced
    float2* dst2 = (float2*)(g_scratch + (((size_t)(b * WR + col)) << 12)) + g * 8 * 32 + lane;
    dst2[0 * 32] = a0; dst2[1 * 32] = a1; dst2[2 * 32] = a2; dst2[3 * 32] = a3;
    dst2[4 * 32] = a4; dst2[5 * 32] = a5; dst2[6 * 32] = a6; dst2[7 * 32] = a7;
}

// scratch [b][col][r][c] -> out [b][c][r][col], -inf -> 0, both sides 128-bit
__global__ void k_final(float* __restrict__ out) {
    __shared__ float tile[32][33];
    int z = blockIdx.z;
    int b = z >> 6;
    int r = z & 63;
    int col0 = blockIdx.x * 32;
    int c0   = blockIdx.y * 32;
    int tx = threadIdx.x;   // 0..7
    int ty = threadIdx.y;   // 0..31
    float4 f = *(const float4*)&g_scratch[(((size_t)(b * WR + col0 + ty)) << 12)
                                          + (r << 6) + c0 + tx * 4];
    tile[tx * 4 + 0][ty] = f.x;
    tile[tx * 4 + 1][ty] = f.y;
    tile[tx * 4 + 2][ty] = f.z;
    tile[tx * 4 + 3][ty] = f.w;
    __syncthreads();
    float4 w;
    w.x = tile[ty][tx * 4 + 0];
    w.y = tile[ty][tx * 4 + 1];
    w.z = tile[ty][tx * 4 + 2];
    w.w = tile[ty][tx * 4 + 3];
    if (w.x == -CUDART_INF_F) w.x = 0.0f;
    if (w.y == -CUDART_INF_F) w.y = 0.0f;
    if (w.z == -CUDART_INF_F) w.z = 0.0f;
    if (w.w == -CUDART_INF_F) w.w = 0.0f;
    *(float4*)&out[(((size_t)(b * NC + c0 + ty)) * HR + r) * WR + col0 + tx * 4] = w;
}

extern "C" void kernel_launch(void* const* d_in, const int* in_sizes, int n_in,
                              void* d_out, int out_size) {
    const float* feat = (const float*)d_in[0];   // [2,64,512,512] f32
    const int*   zbin = (const int*)d_in[1];     // [2,1,512,512] i32
    float*       out  = (float*)d_out;           // [2,64,64,2048] f32

    k_geom<<<NB / 256, 256>>>();
    k_rowhi<<<(NBATCH * NB) / 256, 256>>>(zbin);
    k_transpose<<<dim3(NB / 64, NC / 32, NBATCH), dim3(8, 32)>>>(feat);
    k_project<<<dim3(WR, NBATCH, NG / 2), 64>>>();
    k_final<<<dim3(WR / 32, NC / 32, NBATCH * HR), dim3(8, 32)>>>(out);
}

// round 14
// speedup vs baseline: 1.9583x; 1.0451x over previous
#include <cuda_runtime.h>
#include <cuda_bf16.h>
#include <math.h>
#include <math_constants.h>

#define HB 512
#define WB 512
#define NB (HB*WB)          // 262144 BEV cells
#define NC 64               // channels
#define NBATCH 2
#define HR 64
#define WR 2048
#define NG 8                // row groups (8 rows each)
#define NBKT (NBATCH * WR * NG)
#define CAPF 256            // full-mask bucket capacity (max ~220)
#define CAPP 512            // partial-mask bucket capacity
#define NPAD 12

// device scratch
__device__ float          g_rho[NB];
__device__ unsigned char  g_rowlow[NB];
__device__ unsigned short g_colb[NB];
__device__ int            g_cntF[NBKT];
__device__ int            g_cntP[NBKT];
__device__ unsigned int   g_itemF[(size_t)NBKT * CAPF];  // (cell<<8)|1 ; pad=0
__device__ unsigned int   g_itemP[(size_t)NBKT * CAPP];  // (cell<<8)|mask ; pad=0
__device__ float          g_featT[(size_t)NBATCH * NB * NC];        // [B][N][C]
__device__ float          g_scratch[(size_t)NBATCH * WR * HR * NC]; // [B][col][r][c]

__device__ __forceinline__ float th_maxf()   { return (float)(3.0 * (CUDART_PI / 180.0)); }
__device__ __forceinline__ float th_rangef() {
    double tmax = 3.0 * (CUDART_PI / 180.0);
    double tmin = -25.0 * (CUDART_PI / 180.0);
    return (float)(tmax - tmin);
}
__device__ __forceinline__ float phi_minf()   { return (float)(-CUDART_PI); }
__device__ __forceinline__ float phi_rangef() { return (float)(2.0 * CUDART_PI); }

__device__ __forceinline__ int row_from_theta(float theta) {
    float v = __fmul_rn(__fdiv_rn(__fsub_rn(th_maxf(), theta), th_rangef()), 63.0f);
    v = rintf(v);
    v = fminf(fmaxf(v, 0.0f), 63.0f);
    return (int)v;
}

// ---------------- kernels ----------------
// geometry + zeroing of bucket counters
__global__ void k_geom() {
    int n = blockIdx.x * blockDim.x + threadIdx.x;
    if (n < NBKT) { g_cntF[n] = 0; g_cntP[n] = 0; }
    if (n >= NB) return;
    int i = n >> 9;
    int j = n & 511;
    float y = (float)(((double)i * (-100.0)) / 511.0 + 50.0);
    float x = (float)(((double)j * (100.0)) / 511.0 + (-50.0));
    float rho = __fsqrt_rn(__fadd_rn(__fmul_rn(x, x), __fmul_rn(y, y)));
    float phi = atan2f(y, x);
    float theta_low = atan2f(-1.73f, rho);

    int row_low = row_from_theta(theta_low);

    float cv = __fmul_rn(__fdiv_rn(__fsub_rn(phi, phi_minf()), phi_rangef()), 2047.0f);
    cv = rintf(cv);
    cv = fminf(fmaxf(cv, 0.0f), 2047.0f);
    int col = (int)cv;

    g_rho[n]    = rho;
    g_rowlow[n] = (unsigned char)row_low;
    g_colb[n]   = (unsigned short)col;
}

// per (b,cell): compute [rs,re]; full-mask groups -> F list, partial -> P list
__global__ void k_rowhi(const int* __restrict__ zbin) {
    int idx = blockIdx.x * blockDim.x + threadIdx.x;
    if (idx >= NBATCH * NB) return;
    int n = idx & (NB - 1);
    int b = idx >> 18;
    int zb = zbin[idx];
    float zh = __fadd_rn(__fmul_rn((float)zb, (float)(6.0 / 30.0)),
                         (float)(-4.0 + (6.0 / 30.0) / 2.0));
    float theta_hi = atan2f(zh, g_rho[n]);
    int row_hi  = row_from_theta(theta_hi);
    int row_low = (int)g_rowlow[n];
    int rs = min(row_low, row_hi);
    int re = max(row_low, row_hi);
    int col  = (int)g_colb[n];
    int base = (b * WR + col) * NG;
    int g0 = rs >> 3, g1 = re >> 3;
    unsigned cellhi = (unsigned)n << 8;
    for (int g = g0; g <= g1; ++g) {
        int lo = max(rs - g * 8, 0);
        int hi = min(re - g * 8, 7);
        unsigned mask = (0xFFu >> (7 - hi)) & (0xFFu << lo);
        if (mask == 0xFFu) {
            int pos = atomicAdd(&g_cntF[base + g], 1);
            if (pos < CAPF)
                g_itemF[(size_t)(base + g) * CAPF + pos] = cellhi | 1u;
        } else {
            int pos = atomicAdd(&g_cntP[base + g], 1);
            if (pos < CAPP)
                g_itemP[(size_t)(base + g) * CAPP + pos] = cellhi | mask;
        }
    }
}

// pad each bucket's tail with NPAD inert items so k_project loads unconditionally
__global__ void k_pad() {
    int idx = blockIdx.x * blockDim.x + threadIdx.x;  // (bkt, k)
    int bkt = idx / NPAD;
    int k   = idx - bkt * NPAD;
    if (bkt >= NBKT) return;
    int pf = g_cntF[bkt] + k;
    if (pf < CAPF) g_itemF[(size_t)bkt * CAPF + pf] = 0u;
    int pp = g_cntP[bkt] + k;
    if (pp < CAPP) g_itemP[(size_t)bkt * CAPP + pp] = 0u;
}

// [B,C,N] -> [B,N,C]; 64x32 tile per CTA
__global__ void k_transpose(const float* __restrict__ src) {
    __shared__ float tA[32][33];
    __shared__ float tB[32][33];
    int b  = blockIdx.z;
    int n0 = blockIdx.x * 64;
    int c0 = blockIdx.y * 32;
    int tx = threadIdx.x;   // 0..7
    int ty = threadIdx.y;   // 0..31
    const float* row = &src[((size_t)(b * NC + c0 + ty)) * NB + n0 + tx * 4];
    float4 fa = *(const float4*)row;
    float4 fb = *(const float4*)(row + 32);
    tA[tx * 4 + 0][ty] = fa.x; tA[tx * 4 + 1][ty] = fa.y;
    tA[tx * 4 + 2][ty] = fa.z; tA[tx * 4 + 3][ty] = fa.w;
    tB[tx * 4 + 0][ty] = fb.x; tB[tx * 4 + 1][ty] = fb.y;
    tB[tx * 4 + 2][ty] = fb.z; tB[tx * 4 + 3][ty] = fb.w;
    __syncthreads();
    float4 wa, wb;
    wa.x = tA[ty][tx * 4 + 0]; wa.y = tA[ty][tx * 4 + 1];
    wa.z = tA[ty][tx * 4 + 2]; wa.w = tA[ty][tx * 4 + 3];
    wb.x = tB[ty][tx * 4 + 0]; wb.y = tB[ty][tx * 4 + 1];
    wb.z = tB[ty][tx * 4 + 2]; wb.w = tB[ty][tx * 4 + 3];
    *(float4*)&g_featT[((size_t)b * NB + (n0 + ty)) * NC + c0 + tx * 4]      = wa;
    *(float4*)&g_featT[((size_t)b * NB + (n0 + 32 + ty)) * NC + c0 + tx * 4] = wb;
}

// CTA = (colperm, b, gpair): 64 threads = 2 warps = 2 row groups.
// Lane owns 2 channels. Full-mask items use a single accumulator pair;
// partial items use the 8-row masked path. All loads unconditional (pads).
__global__ void __launch_bounds__(64) k_project() {
    int col = (blockIdx.x * 331) & (WR - 1);   // spread heavy columns
    int b   = blockIdx.y;
    int g    = blockIdx.z * 2 + (threadIdx.x >> 5);
    int lane = threadIdx.x & 31;

    const float NF = -CUDART_INF_F;
    float2 a0 = make_float2(NF, NF);
    float2 a1 = a0, a2 = a0, a3 = a0, a4 = a0, a5 = a0, a6 = a0, a7 = a0;
    float2 af = a0;   // full-mask accumulator (all 8 rows)

    int bkt  = (b * WR + col) * NG + g;
    int cntF = min(g_cntF[bkt], CAPF - NPAD);
    int cntP = min(g_cntP[bkt], CAPP - NPAD);
    const unsigned* itemsF = g_itemF + (size_t)bkt * CAPF;
    const unsigned* itemsP = g_itemP + (size_t)bkt * CAPP;
    const char* featc = (const char*)g_featT + ((size_t)b * NB * NC + lane * 2) * 4;

#define FLOAD(IT) (*(const float2*)(featc + (size_t)((IT) & 0xFFFFFF00u)))

    unsigned itA[4], itB[4];
    float2   vA[4],  vB[4];

    // ================= full-mask loop =================
    #pragma unroll
    for (int k = 0; k < 4; ++k) { itA[k] = __ldg(&itemsF[k]); vA[k] = FLOAD(itA[k]); }
    for (int base = 0; base < cntF; base += 8) {
        #pragma unroll
        for (int k = 0; k < 4; ++k) {
            itB[k] = __ldg(&itemsF[base + 4 + k]); vB[k] = FLOAD(itB[k]);
        }
        #pragma unroll
        for (int k = 0; k < 4; ++k)
            if (itA[k] & 1u) { af.x = fmaxf(af.x, vA[k].x); af.y = fmaxf(af.y, vA[k].y); }
        #pragma unroll
        for (int k = 0; k < 4; ++k) {
            itA[k] = __ldg(&itemsF[base + 8 + k]); vA[k] = FLOAD(itA[k]);
        }
        #pragma unroll
        for (int k = 0; k < 4; ++k)
            if (itB[k] & 1u) { af.x = fmaxf(af.x, vB[k].x); af.y = fmaxf(af.y, vB[k].y); }
    }

    // ================= partial-mask loop =================
#define UPDATE(IT, V) do {                                                     \
        unsigned _m = (IT) & 0xFFu;                                            \
        float2 _v = (V);                                                       \
        if (_m & 0x01u) { a0.x = fmaxf(a0.x, _v.x); a0.y = fmaxf(a0.y, _v.y); }\
        if (_m & 0x02u) { a1.x = fmaxf(a1.x, _v.x); a1.y = fmaxf(a1.y, _v.y); }\
        if (_m & 0x04u) { a2.x = fmaxf(a2.x, _v.x); a2.y = fmaxf(a2.y, _v.y); }\
        if (_m & 0x08u) { a3.x = fmaxf(a3.x, _v.x); a3.y = fmaxf(a3.y, _v.y); }\
        if (_m & 0x10u) { a4.x = fmaxf(a4.x, _v.x); a4.y = fmaxf(a4.y, _v.y); }\
        if (_m & 0x20u) { a5.x = fmaxf(a5.x, _v.x); a5.y = fmaxf(a5.y, _v.y); }\
        if (_m & 0x40u) { a6.x = fmaxf(a6.x, _v.x); a6.y = fmaxf(a6.y, _v.y); }\
        if (_m & 0x80u) { a7.x = fmaxf(a7.x, _v.x); a7.y = fmaxf(a7.y, _v.y); }\
    } while (0)

    #pragma unroll
    for (int k = 0; k < 4; ++k) { itA[k] = __ldg(&itemsP[k]); vA[k] = FLOAD(itA[k]); }
    for (int base = 0; base < cntP; base += 8) {
        #pragma unroll
        for (int k = 0; k < 4; ++k) {
            itB[k] = __ldg(&itemsP[base + 4 + k]); vB[k] = FLOAD(itB[k]);
        }
        #pragma unroll
        for (int k = 0; k < 4; ++k) UPDATE(itA[k], vA[k]);
        #pragma unroll
        for (int k = 0; k < 4; ++k) {
            itA[k] = __ldg(&itemsP[base + 8 + k]); vA[k] = FLOAD(itA[k]);
        }
        #pragma unroll
        for (int k = 0; k < 4; ++k) UPDATE(itB[k], vB[k]);
    }
#undef UPDATE
#undef FLOAD

    // merge full accumulator into all rows
    a0.x = fmaxf(a0.x, af.x); a0.y = fmaxf(a0.y, af.y);
    a1.x = fmaxf(a1.x, af.x); a1.y = fmaxf(a1.y, af.y);
    a2.x = fmaxf(a2.x, af.x); a2.y = fmaxf(a2.y, af.y);
    a3.x = fmaxf(a3.x, af.x); a3.y = fmaxf(a3.y, af.y);
    a4.x = fmaxf(a4.x, af.x); a4.y = fmaxf(a4.y, af.y);
    a5.x = fmaxf(a5.x, af.x); a5.y = fmaxf(a5.y, af.y);
    a6.x = fmaxf(a6.x, af.x); a6.y = fmaxf(a6.y, af.y);
    a7.x = fmaxf(a7.x, af.x); a7.y = fmaxf(a7.y, af.y);

    // epilogue: scratch [b][col][r][c], coalesced
    float2* dst2 = (float2*)(g_scratch + (((size_t)(b * WR + col)) << 12)) + g * 8 * 32 + lane;
    dst2[0 * 32] = a0; dst2[1 * 32] = a1; dst2[2 * 32] = a2; dst2[3 * 32] = a3;
    dst2[4 * 32] = a4; dst2[5 * 32] = a5; dst2[6 * 32] = a6; dst2[7 * 32] = a7;
}

// scratch [b][col][r][c] -> out [b][c][r][col], -inf -> 0, both sides 128-bit
__global__ void k_final(float* __restrict__ out) {
    __shared__ float tile[32][33];
    int z = blockIdx.z;
    int b = z >> 6;
    int r = z & 63;
    int col0 = blockIdx.x * 32;
    int c0   = blockIdx.y * 32;
    int tx = threadIdx.x;   // 0..7
    int ty = threadIdx.y;   // 0..31
    float4 f = *(const float4*)&g_scratch[(((size_t)(b * WR + col0 + ty)) << 12)
                                          + (r << 6) + c0 + tx * 4];
    tile[tx * 4 + 0][ty] = f.x;
    tile[tx * 4 + 1][ty] = f.y;
    tile[tx * 4 + 2][ty] = f.z;
    tile[tx * 4 + 3][ty] = f.w;
    __syncthreads();
    float4 w;
    w.x = tile[ty][tx * 4 + 0];
    w.y = tile[ty][tx * 4 + 1];
    w.z = tile[ty][tx * 4 + 2];
    w.w = tile[ty][tx * 4 + 3];
    if (w.x == -CUDART_INF_F) w.x = 0.0f;
    if (w.y == -CUDART_INF_F) w.y = 0.0f;
    if (w.z == -CUDART_INF_F) w.z = 0.0f;
    if (w.w == -CUDART_INF_F) w.w = 0.0f;
    *(float4*)&out[(((size_t)(b * NC + c0 + ty)) * HR + r) * WR + col0 + tx * 4] = w;
}

extern "C" void kernel_launch(void* const* d_in, const int* in_sizes, int n_in,
                              void* d_out, int out_size) {
    const float* feat = (const float*)d_in[0];   // [2,64,512,512] f32
    const int*   zbin = (const int*)d_in[1];     // [2,1,512,512] i32
    float*       out  = (float*)d_out;           // [2,64,64,2048] f32

    k_geom<<<NB / 256, 256>>>();
    k_rowhi<<<(NBATCH * NB) / 256, 256>>>(zbin);
    k_pad<<<(NBKT * NPAD + 255) / 256, 256>>>();
    k_transpose<<<dim3(NB / 64, NC / 32, NBATCH), dim3(8, 32)>>>(feat);
    k_project<<<dim3(WR, NBATCH, NG / 2), 64>>>();
    k_final<<<dim3(WR / 32, NC / 32, NBATCH * HR), dim3(8, 32)>>>(out);
}

// round 17
// speedup vs baseline: 2.3777x; 1.2141x over previous
#include <cuda_runtime.h>
#include <cuda_bf16.h>
#include <cuda_fp16.h>
#include <math.h>
#include <math_constants.h>

#define HB 512
#define WB 512
#define NB (HB*WB)          // 262144 BEV cells
#define NC 64               // channels
#define NBATCH 2
#define HR 64
#define WR 2048
#define NG 8                // row groups (8 rows each)
#define NBKT (NBATCH * WR * NG)
#define CAPF 256            // full-mask bucket capacity (max ~220)
#define CAPP 512            // partial-mask bucket capacity
#define NPAD 12

// device scratch
__device__ float          g_rho[NB];
__device__ unsigned char  g_rowlow[NB];
__device__ unsigned short g_colb[NB];
__device__ int            g_cntF[NBKT];
__device__ int            g_cntP[NBKT];
__device__ unsigned int   g_itemF[(size_t)NBKT * CAPF];  // (cell<<8)|1 ; pad=0
__device__ unsigned int   g_itemP[(size_t)NBKT * CAPP];  // (cell<<8)|mask ; pad=0
__device__ __half         g_featH[(size_t)NBATCH * NB * NC];        // [B][N][C] fp16
__device__ __half         g_scratchH[(size_t)NBATCH * WR * HR * NC]; // [B][col][r][c] fp16

__device__ __forceinline__ float th_maxf()   { return (float)(3.0 * (CUDART_PI / 180.0)); }
__device__ __forceinline__ float th_rangef() {
    double tmax = 3.0 * (CUDART_PI / 180.0);
    double tmin = -25.0 * (CUDART_PI / 180.0);
    return (float)(tmax - tmin);
}
__device__ __forceinline__ float phi_minf()   { return (float)(-CUDART_PI); }
__device__ __forceinline__ float phi_rangef() { return (float)(2.0 * CUDART_PI); }

__device__ __forceinline__ int row_from_theta(float theta) {
    float v = __fmul_rn(__fdiv_rn(__fsub_rn(th_maxf(), theta), th_rangef()), 63.0f);
    v = rintf(v);
    v = fminf(fmaxf(v, 0.0f), 63.0f);
    return (int)v;
}

__device__ __forceinline__ __half2 h2_neginf() {
    unsigned u = 0xFC00FC00u;
    return *reinterpret_cast<__half2*>(&u);
}

// ---------------- kernels ----------------
// geometry + zeroing of bucket counters
__global__ void k_geom() {
    int n = blockIdx.x * blockDim.x + threadIdx.x;
    if (n < NBKT) { g_cntF[n] = 0; g_cntP[n] = 0; }
    if (n >= NB) return;
    int i = n >> 9;
    int j = n & 511;
    float y = (float)(((double)i * (-100.0)) / 511.0 + 50.0);
    float x = (float)(((double)j * (100.0)) / 511.0 + (-50.0));
    float rho = __fsqrt_rn(__fadd_rn(__fmul_rn(x, x), __fmul_rn(y, y)));
    float phi = atan2f(y, x);
    float theta_low = atan2f(-1.73f, rho);

    int row_low = row_from_theta(theta_low);

    float cv = __fmul_rn(__fdiv_rn(__fsub_rn(phi, phi_minf()), phi_rangef()), 2047.0f);
    cv = rintf(cv);
    cv = fminf(fmaxf(cv, 0.0f), 2047.0f);
    int col = (int)cv;

    g_rho[n]    = rho;
    g_rowlow[n] = (unsigned char)row_low;
    g_colb[n]   = (unsigned short)col;
}

// per (b,cell): compute [rs,re]; full-mask groups -> F list, partial -> P list
__global__ void k_rowhi(const int* __restrict__ zbin) {
    int idx = blockIdx.x * blockDim.x + threadIdx.x;
    if (idx >= NBATCH * NB) return;
    int n = idx & (NB - 1);
    int b = idx >> 18;
    int zb = zbin[idx];
    float zh = __fadd_rn(__fmul_rn((float)zb, (float)(6.0 / 30.0)),
                         (float)(-4.0 + (6.0 / 30.0) / 2.0));
    float theta_hi = atan2f(zh, g_rho[n]);
    int row_hi  = row_from_theta(theta_hi);
    int row_low = (int)g_rowlow[n];
    int rs = min(row_low, row_hi);
    int re = max(row_low, row_hi);
    int col  = (int)g_colb[n];
    int base = (b * WR + col) * NG;
    int g0 = rs >> 3, g1 = re >> 3;
    unsigned cellhi = (unsigned)n << 8;
    for (int g = g0; g <= g1; ++g) {
        int lo = max(rs - g * 8, 0);
        int hi = min(re - g * 8, 7);
        unsigned mask = (0xFFu >> (7 - hi)) & (0xFFu << lo);
        if (mask == 0xFFu) {
            int pos = atomicAdd(&g_cntF[base + g], 1);
            if (pos < CAPF)
                g_itemF[(size_t)(base + g) * CAPF + pos] = cellhi | 1u;
        } else {
            int pos = atomicAdd(&g_cntP[base + g], 1);
            if (pos < CAPP)
                g_itemP[(size_t)(base + g) * CAPP + pos] = cellhi | mask;
        }
    }
}

// pad each bucket's tail with NPAD inert items so k_project loads unconditionally
__global__ void k_pad() {
    int idx = blockIdx.x * blockDim.x + threadIdx.x;  // (bkt, k)
    int bkt = idx / NPAD;
    int k   = idx - bkt * NPAD;
    if (bkt >= NBKT) return;
    int pf = g_cntF[bkt] + k;
    if (pf < CAPF) g_itemF[(size_t)bkt * CAPF + pf] = 0u;
    int pp = g_cntP[bkt] + k;
    if (pp < CAPP) g_itemP[(size_t)bkt * CAPP + pp] = 0u;
}

// [B,C,N] f32 -> [B,N,C] fp16; 64x32 tile per CTA
__global__ void k_transpose(const float* __restrict__ src) {
    __shared__ float tA[32][33];
    __shared__ float tB[32][33];
    int b  = blockIdx.z;
    int n0 = blockIdx.x * 64;
    int c0 = blockIdx.y * 32;
    int tx = threadIdx.x;   // 0..7
    int ty = threadIdx.y;   // 0..31
    const float* row = &src[((size_t)(b * NC + c0 + ty)) * NB + n0 + tx * 4];
    float4 fa = *(const float4*)row;
    float4 fb = *(const float4*)(row + 32);
    tA[tx * 4 + 0][ty] = fa.x; tA[tx * 4 + 1][ty] = fa.y;
    tA[tx * 4 + 2][ty] = fa.z; tA[tx * 4 + 3][ty] = fa.w;
    tB[tx * 4 + 0][ty] = fb.x; tB[tx * 4 + 1][ty] = fb.y;
    tB[tx * 4 + 2][ty] = fb.z; tB[tx * 4 + 3][ty] = fb.w;
    __syncthreads();
    float4 wa, wb;
    wa.x = tA[ty][tx * 4 + 0]; wa.y = tA[ty][tx * 4 + 1];
    wa.z = tA[ty][tx * 4 + 2]; wa.w = tA[ty][tx * 4 + 3];
    wb.x = tB[ty][tx * 4 + 0]; wb.y = tB[ty][tx * 4 + 1];
    wb.z = tB[ty][tx * 4 + 2]; wb.w = tB[ty][tx * 4 + 3];
    __half2 ha0 = __float22half2_rn(make_float2(wa.x, wa.y));
    __half2 ha1 = __float22half2_rn(make_float2(wa.z, wa.w));
    __half2 hb0 = __float22half2_rn(make_float2(wb.x, wb.y));
    __half2 hb1 = __float22half2_rn(make_float2(wb.z, wb.w));
    uint2 ua = make_uint2(*(unsigned*)&ha0, *(unsigned*)&ha1);
    uint2 ub = make_uint2(*(unsigned*)&hb0, *(unsigned*)&hb1);
    *(uint2*)&g_featH[((size_t)b * NB + (n0 + ty)) * NC + c0 + tx * 4]      = ua;
    *(uint2*)&g_featH[((size_t)b * NB + (n0 + 32 + ty)) * NC + c0 + tx * 4] = ub;
}

// CTA = (colperm, b, gpair): 64 threads = 2 warps = 2 row groups.
// Lane owns a channel pair in ONE half2 accumulator (packed HMNMX2 max).
__global__ void __launch_bounds__(64) k_project() {
    int col = (blockIdx.x * 331) & (WR - 1);   // spread heavy columns
    int b   = blockIdx.y;
    int g    = blockIdx.z * 2 + (threadIdx.x >> 5);
    int lane = threadIdx.x & 31;

    __half2 a0 = h2_neginf(), a1 = a0, a2 = a0, a3 = a0,
            a4 = a0, a5 = a0, a6 = a0, a7 = a0, af = a0;

    int bkt  = (b * WR + col) * NG + g;
    int cntF = min(g_cntF[bkt], CAPF - NPAD);
    int cntP = min(g_cntP[bkt], CAPP - NPAD);
    const unsigned* itemsF = g_itemF + (size_t)bkt * CAPF;
    const unsigned* itemsP = g_itemP + (size_t)bkt * CAPP;
    // per-lane fp16 feature base: batch offset + this lane's channel pair
    const char* featc = (const char*)g_featH + ((size_t)b * NB * NC + lane * 2) * 2;

    // item's cell<<8 is cell*256; fp16 row is 128 B -> byte offset = field >> 1
#define FLOAD(IT) (*(const __half2*)(featc + ((size_t)((IT) & 0xFFFFFF00u) >> 1)))

    unsigned itA[4], itB[4];
    __half2  vA[4],  vB[4];

    // ================= full-mask loop =================
    #pragma unroll
    for (int k = 0; k < 4; ++k) { itA[k] = __ldg(&itemsF[k]); vA[k] = FLOAD(itA[k]); }
    for (int base = 0; base < cntF; base += 8) {
        #pragma unroll
        for (int k = 0; k < 4; ++k) {
            itB[k] = __ldg(&itemsF[base + 4 + k]); vB[k] = FLOAD(itB[k]);
        }
        #pragma unroll
        for (int k = 0; k < 4; ++k)
            if (itA[k] & 1u) af = __hmax2(af, vA[k]);
        #pragma unroll
        for (int k = 0; k < 4; ++k) {
            itA[k] = __ldg(&itemsF[base + 8 + k]); vA[k] = FLOAD(itA[k]);
        }
        #pragma unroll
        for (int k = 0; k < 4; ++k)
            if (itB[k] & 1u) af = __hmax2(af, vB[k]);
    }

    // ================= partial-mask loop =================
#define UPDATE(IT, V) do {                                                     \
        unsigned _m = (IT);                                                    \
        __half2 _v = (V);                                                      \
        if (_m & 0x01u) a0 = __hmax2(a0, _v);                                  \
        if (_m & 0x02u) a1 = __hmax2(a1, _v);                                  \
        if (_m & 0x04u) a2 = __hmax2(a2, _v);                                  \
        if (_m & 0x08u) a3 = __hmax2(a3, _v);                                  \
        if (_m & 0x10u) a4 = __hmax2(a4, _v);                                  \
        if (_m & 0x20u) a5 = __hmax2(a5, _v);                                  \
        if (_m & 0x40u) a6 = __hmax2(a6, _v);                                  \
        if (_m & 0x80u) a7 = __hmax2(a7, _v);                                  \
    } while (0)

    #pragma unroll
    for (int k = 0; k < 4; ++k) { itA[k] = __ldg(&itemsP[k]); vA[k] = FLOAD(itA[k]); }
    for (int base = 0; base < cntP; base += 8) {
        #pragma unroll
        for (int k = 0; k < 4; ++k) {
            itB[k] = __ldg(&itemsP[base + 4 + k]); vB[k] = FLOAD(itB[k]);
        }
        #pragma unroll
        for (int k = 0; k < 4; ++k) UPDATE(itA[k], vA[k]);
        #pragma unroll
        for (int k = 0; k < 4; ++k) {
            itA[k] = __ldg(&itemsP[base + 8 + k]); vA[k] = FLOAD(itA[k]);
        }
        #pragma unroll
        for (int k = 0; k < 4; ++k) UPDATE(itB[k], vB[k]);
    }
#undef UPDATE
#undef FLOAD

    // merge full accumulator into all rows
    a0 = __hmax2(a0, af); a1 = __hmax2(a1, af);
    a2 = __hmax2(a2, af); a3 = __hmax2(a3, af);
    a4 = __hmax2(a4, af); a5 = __hmax2(a5, af);
    a6 = __hmax2(a6, af); a7 = __hmax2(a7, af);

    // epilogue: scratch fp16 [b][col][r][c], coalesced (128 B/warp-row)
    __half2* dst2 = (__half2*)g_scratchH + ((size_t)(b * WR + col) * 2048) + g * 8 * 32 + lane;
    dst2[0 * 32] = a0; dst2[1 * 32] = a1; dst2[2 * 32] = a2; dst2[3 * 32] = a3;
    dst2[4 * 32] = a4; dst2[5 * 32] = a5; dst2[6 * 32] = a6; dst2[7 * 32] = a7;
}

// scratch fp16 [b][col][r][c] -> out f32 [b][c][r][col], -inf -> 0
__global__ void k_final(float* __restrict__ out) {
    __shared__ float tile[32][33];
    int z = blockIdx.z;
    int b = z >> 6;
    int r = z & 63;
    int col0 = blockIdx.x * 32;
    int c0   = blockIdx.y * 32;
    int tx = threadIdx.x;   // 0..7
    int ty = threadIdx.y;   // 0..31
    uint2 u = *(const uint2*)&g_scratchH[(((size_t)(b * WR + col0 + ty)) << 12)
                                         + (r << 6) + c0 + tx * 4];
    __half2 h0 = *(__half2*)&u.x;
    __half2 h1 = *(__half2*)&u.y;
    float2 f0 = __half22float2(h0);
    float2 f1 = __half22float2(h1);
    tile[tx * 4 + 0][ty] = f0.x;
    tile[tx * 4 + 1][ty] = f0.y;
    tile[tx * 4 + 2][ty] = f1.x;
    tile[tx * 4 + 3][ty] = f1.y;
    __syncthreads();
    float4 w;
    w.x = tile[ty][tx * 4 + 0];
    w.y = tile[ty][tx * 4 + 1];
    w.z = tile[ty][tx * 4 + 2];
    w.w = tile[ty][tx * 4 + 3];
    if (w.x == -CUDART_INF_F) w.x = 0.0f;
    if (w.y == -CUDART_INF_F) w.y = 0.0f;
    if (w.z == -CUDART_INF_F) w.z = 0.0f;
    if (w.w == -CUDART_INF_F) w.w = 0.0f;
    *(float4*)&out[(((size_t)(b * NC + c0 + ty)) * HR + r) * WR + col0 + tx * 4] = w;
}

extern "C" void kernel_launch(void* const* d_in, const int* in_sizes, int n_in,
                              void* d_out, int out_size) {
    const float* feat = (const float*)d_in[0];   // [2,64,512,512] f32
    const int*   zbin = (const int*)d_in[1];     // [2,1,512,512] i32
    float*       out  = (float*)d_out;           // [2,64,64,2048] f32

    k_geom<<<NB / 256, 256>>>();
    k_rowhi<<<(NBATCH * NB) / 256, 256>>>(zbin);
    k_pad<<<(NBKT * NPAD + 255) / 256, 256>>>();
    k_transpose<<<dim3(NB / 64, NC / 32, NBATCH), dim3(8, 32)>>>(feat);
    k_project<<<dim3(WR, NBATCH, NG / 2), 64>>>();
    k_final<<<dim3(WR / 32, NC / 32, NBATCH * HR), dim3(8, 32)>>>(out);
}